// round 14
// baseline (speedup 1.0000x reference)
#include <cuda_runtime.h>
#include <cuda_fp16.h>

#define HW     131072      // h*w = 256*512
#define C      128
#define LTOT   163840      // Q*M*M
#define KS     9
#define TLB    32          // l-values per block
#define WPB    8           // warps per block
#define ROUNDS (TLB/WPB)
#define NTASK  (TLB*KS)    // 288 codes per block
#define OSTR   132         // padded staging stride (words) per l row
#define PLANE  16384       // M*M
#define NB     16          // BN stat buckets
#define NBLK   (LTOT/TLB)  // 5120 main blocks

// Scratch (allocation-free rule: device globals)
__device__ __align__(16) __half g_xh[(size_t)HW * C];     // transposed x (fp16): [hw][c]
__device__ __align__(16) __half g_oh[(size_t)LTOT * C];   // pre-BN output (fp16)
__device__ __align__(8)  float2 g_stat[HW];               // per-position (mean, max), fp32
__device__ __align__(16) float  g_wt[KS * C];             // depth_w transposed: [k][c]
__device__ float g_sumf[C * NB];
__device__ float g_sumsqf[C * NB];
__device__ float g_a[C];
__device__ float g_b[C];

// ---------------------------------------------------------------------------
// Tiny setup kernels (also steer ncu capture so main_k is launch #4)
__global__ void zero_k() {
    int i = threadIdx.x;
    for (; i < C * NB; i += 256) { g_sumf[i] = 0.f; g_sumsqf[i] = 0.f; }
}
__global__ void wt_k(const float* __restrict__ depth_w) {
    int i = threadIdx.x;
    for (; i < KS * C; i += 256) {
        int k = i / C, c = i % C;
        g_wt[k * C + c] = depth_w[c * KS + k];
    }
}

// ---------------------------------------------------------------------------
// x [C][HW] -> g_xh [HW][C] (fp16), fused fp32 per-position mean/max -> g_stat.
__global__ void __launch_bounds__(256) transpose_k(const float* __restrict__ x) {
    __shared__ float tile[C][33];          // [c][hw_local]
    __shared__ float sms[8][32];
    __shared__ float smm[8][32];
    const int hw0 = blockIdx.x * 32;
    const int t  = threadIdx.x;
    const int tx = t & 31, ty = t >> 5;

    float s = 0.f, m = -3.4e38f;
#pragma unroll
    for (int i = 0; i < C; i += 8) {
        float v = __ldcs(x + (size_t)(i + ty) * HW + hw0 + tx);
        tile[i + ty][tx] = v;
        s += v;
        m = fmaxf(m, v);
    }
    sms[ty][tx] = s;
    smm[ty][tx] = m;
    __syncthreads();

    const int hwl = t >> 6;
    const int cp  = t & 63;
#pragma unroll
    for (int i = 0; i < 32; i += 4) {
        const int hw = hwl + i;
        __half2 h = __floats2half2_rn(tile[cp * 2][hw], tile[cp * 2 + 1][hw]);
        *(__half2*)(g_xh + (size_t)(hw0 + hw) * C + cp * 2) = h;
    }
    if (ty == 0) {
        float S = 0.f, M = -3.4e38f;
#pragma unroll
        for (int j = 0; j < 8; j++) { S += sms[j][tx]; M = fmaxf(M, smm[j][tx]); }
        g_stat[hw0 + tx] = make_float2(S * (1.0f / C), M);
    }
}

// ---------------------------------------------------------------------------
// One block = 32 l values. L1-wavefront diet (r13 profile: L1TEX-bound):
//  - phase 2: one thread per l, stats in registers (deletes 2592 LDS/block)
//  - depthwise w in registers (no per-l LDS.128), gathers chunked 5+4
__global__ void __launch_bounds__(256, 4) main_k(
    const int*   __restrict__ codes,
    const float* __restrict__ att_w,   // [KS][2][KS]
    const float* __restrict__ att_b,   // [KS]
    const float* __restrict__ depth_b) // [C]
{
    __shared__ float  sm_out[TLB * OSTR];   // [l_local][c] staging
    __shared__ float  sm_attp[NTASK];       // 1+sigmoid per (l,o)
    __shared__ float  sm_aw[KS * 2 * KS];
    __shared__ float  sm_ab[KS];
    __shared__ int    sidx[NTASK];

    const int t    = threadIdx.x;
    const int wid  = t >> 5;
    const int lane = t & 31;
    const int l0   = blockIdx.x * TLB;
    const int c0   = lane * 4;

    if (t < KS * 2 * KS) sm_aw[t] = att_w[t];
    if (t < KS)          sm_ab[t] = att_b[t];

    // depthwise weights in registers (channels c0..c0+3, all 9 k)
    float4 wr[KS];
#pragma unroll
    for (int k = 0; k < KS; k++)
        wr[k] = *(const float4*)(g_wt + k * C + c0);

    // phase 1: codes
    for (int i = t; i < NTASK; i += 256)
        sidx[i] = __ldg(codes + l0 * KS + i);
    __syncthreads();

    // phase 2: one thread per l; stats register-resident
    if (t < TLB) {
        float2 st[KS];
#pragma unroll
        for (int k = 0; k < KS; k++)
            st[k] = g_stat[sidx[t * KS + k]];
#pragma unroll
        for (int o = 0; o < KS; o++) {
            float a = sm_ab[o];
#pragma unroll
            for (int k = 0; k < KS; k++)
                a += st[k].x * sm_aw[(o * 2    ) * KS + k]
                   + st[k].y * sm_aw[(o * 2 + 1) * KS + k];
            sm_attp[t * KS + o] = 1.0f + 1.0f / (1.0f + __expf(-a));
        }
    }
    __syncthreads();

    // phase 3: chunked gathers (5+4) + depthwise with register weights
#pragma unroll
    for (int r = 0; r < ROUNDS; r++) {
        const int ll = r * WPB + wid;
        float4 acc = make_float4(0.f, 0.f, 0.f, 0.f);
        uint2 v[5];

#pragma unroll
        for (int k = 0; k < 5; k++) {
            int j = sidx[ll * KS + k];
            v[k] = *(const uint2*)(g_xh + (size_t)j * C + c0);
        }
#pragma unroll
        for (int k = 0; k < 5; k++) {
            const float apk = sm_attp[ll * KS + k];
            float2 x01 = __half22float2(*(__half2*)&v[k].x);
            float2 x23 = __half22float2(*(__half2*)&v[k].y);
            acc.x = fmaf(x01.x, apk * wr[k].x, acc.x);
            acc.y = fmaf(x01.y, apk * wr[k].y, acc.y);
            acc.z = fmaf(x23.x, apk * wr[k].z, acc.z);
            acc.w = fmaf(x23.y, apk * wr[k].w, acc.w);
        }
#pragma unroll
        for (int k = 0; k < 4; k++) {
            int j = sidx[ll * KS + 5 + k];
            v[k] = *(const uint2*)(g_xh + (size_t)j * C + c0);
        }
#pragma unroll
        for (int k = 0; k < 4; k++) {
            const float apk = sm_attp[ll * KS + 5 + k];
            float2 x01 = __half22float2(*(__half2*)&v[k].x);
            float2 x23 = __half22float2(*(__half2*)&v[k].y);
            acc.x = fmaf(x01.x, apk * wr[5 + k].x, acc.x);
            acc.y = fmaf(x01.y, apk * wr[5 + k].y, acc.y);
            acc.z = fmaf(x23.x, apk * wr[5 + k].z, acc.z);
            acc.w = fmaf(x23.y, apk * wr[5 + k].w, acc.w);
        }
        *(float4*)(sm_out + ll * OSTR + c0) = acc;
    }
    __syncthreads();

    // epilogue: conflict-free LDS (half rows offset by 4), plain fp16 stores,
    // float BN-stat atomics
    const int c    = t >> 1;
    const int half = t & 1;
    const int q    = l0 >> 14;
    const int rbase = l0 & (PLANE - 1);
    const float dbc = depth_b[c];
    __half* ob = g_oh + (size_t)q * (C * PLANE) + (size_t)c * PLANE + rbase;

    float s1 = 0.f, s2 = 0.f;
#pragma unroll
    for (int i = 0; i < 4; i++) {
        const int rb = half * 4 + i * 8;      // rows rb..rb+3
        float4 o4;
        o4.x = sm_out[(rb + 0) * OSTR + c] + dbc;
        o4.y = sm_out[(rb + 1) * OSTR + c] + dbc;
        o4.z = sm_out[(rb + 2) * OSTR + c] + dbc;
        o4.w = sm_out[(rb + 3) * OSTR + c] + dbc;
        s1 += (o4.x + o4.y) + (o4.z + o4.w);
        s2 += o4.x * o4.x + o4.y * o4.y + o4.z * o4.z + o4.w * o4.w;
        __half2 h01 = __floats2half2_rn(o4.x, o4.y);
        __half2 h23 = __floats2half2_rn(o4.z, o4.w);
        *(uint2*)(ob + rb) = make_uint2(*(unsigned*)&h01, *(unsigned*)&h23);
    }

    s1 += __shfl_xor_sync(0xffffffffu, s1, 1);
    s2 += __shfl_xor_sync(0xffffffffu, s2, 1);
    if (half == 0) {
        const int bkt = blockIdx.x & (NB - 1);
        atomicAdd(&g_sumf[c * NB + bkt],   s1);
        atomicAdd(&g_sumsqf[c * NB + bkt], s2);
    }
}

// ---------------------------------------------------------------------------
__global__ void bn_params_k(const float* __restrict__ gamma,
                            const float* __restrict__ beta) {
    int t = threadIdx.x;
    int c = t >> 1, half = t & 1;
    double s1 = 0.0, s2 = 0.0;
#pragma unroll
    for (int b = 0; b < NB / 2; b++) {
        int idx = c * NB + half * (NB / 2) + b;
        s1 += (double)g_sumf[idx]; s2 += (double)g_sumsqf[idx];
    }
    s1 += __shfl_xor_sync(0xffffffffu, s1, 1);
    s2 += __shfl_xor_sync(0xffffffffu, s2, 1);
    if (half == 0) {
        double mean = s1 * (1.0 / LTOT);
        double var  = s2 * (1.0 / LTOT) - mean * mean;
        float inv = rsqrtf((float)var + 1e-5f);
        float a = gamma[c] * inv;
        g_a[c] = a;
        g_b[c] = beta[c] - (float)mean * a;
    }
}

// ---------------------------------------------------------------------------
__device__ __forceinline__ float silu_f(float v) {
    return __fdividef(v, 1.f + __expf(-v));
}

__global__ void finalize_k(float* __restrict__ out) {
    const int i = blockIdx.x * blockDim.x + threadIdx.x;   // 8-half chunk index
    const size_t base = (size_t)i * 8;
    const int c = (int)((base >> 14) & 127);               // (base/PLANE)%C
    const float a = g_a[c], b = g_b[c];

    uint4 h = *((const uint4*)g_oh + i);
    float2 p0 = __half22float2(*(__half2*)&h.x);
    float2 p1 = __half22float2(*(__half2*)&h.y);
    float2 p2 = __half22float2(*(__half2*)&h.z);
    float2 p3 = __half22float2(*(__half2*)&h.w);

    float4 r0, r1;
    r0.x = silu_f(fmaf(a, p0.x, b));
    r0.y = silu_f(fmaf(a, p0.y, b));
    r0.z = silu_f(fmaf(a, p1.x, b));
    r0.w = silu_f(fmaf(a, p1.y, b));
    r1.x = silu_f(fmaf(a, p2.x, b));
    r1.y = silu_f(fmaf(a, p2.y, b));
    r1.z = silu_f(fmaf(a, p3.x, b));
    r1.w = silu_f(fmaf(a, p3.y, b));

    __stcs((float4*)out + i * 2,     r0);
    __stcs((float4*)out + i * 2 + 1, r1);
}

// ---------------------------------------------------------------------------
extern "C" void kernel_launch(void* const* d_in, const int* in_sizes, int n_in,
                              void* d_out, int out_size) {
    const float* x       = (const float*)d_in[0];
    const int*   codes   = (const int*)  d_in[1];
    const float* att_w   = (const float*)d_in[2];
    const float* att_b   = (const float*)d_in[3];
    const float* depth_w = (const float*)d_in[4];
    const float* depth_b = (const float*)d_in[5];
    const float* gamma   = (const float*)d_in[6];
    const float* beta    = (const float*)d_in[7];
    float* out = (float*)d_out;

    zero_k<<<1, 256>>>();                              // launch 1
    wt_k<<<1, 256>>>(depth_w);                         // launch 2
    transpose_k<<<HW / 32, 256>>>(x);                  // launch 3
    main_k<<<NBLK, 256>>>(codes, att_w, att_b, depth_b);   // launch 4 <- ncu
    bn_params_k<<<1, 256>>>(gamma, beta);              // launch 5
    finalize_k<<<(LTOT * C / 8) / 256, 256>>>(out);    // launch 6
}

// round 15
// speedup vs baseline: 1.0880x; 1.0880x over previous
#include <cuda_runtime.h>
#include <cuda_fp16.h>

#define HW     131072      // h*w = 256*512
#define C      128
#define LTOT   163840      // Q*M*M
#define KS     9
#define TLB    32          // l-values per block
#define WPB    8           // warps per block
#define ROUNDS (TLB/WPB)
#define NTASK  (TLB*KS)    // 288 (l,k)/(l,o) tasks per block
#define OSTR   132         // padded staging stride (words) per l row
#define PLANE  16384       // M*M
#define NB     16          // BN stat buckets
#define NBLK   (LTOT/TLB)  // 5120 main blocks

// Scratch (allocation-free rule: device globals)
__device__ __align__(16) __half g_xh[(size_t)HW * C];     // transposed x (fp16): [hw][c]
__device__ __align__(16) __half g_oh[(size_t)LTOT * C];   // pre-BN output (fp16)
__device__ __align__(8)  float2 g_stat[HW];               // per-position (mean, max), fp32
__device__ __align__(16) float  g_wt[KS * C];             // depth_w transposed: [k][c]
__device__ float g_sumf[C * NB];
__device__ float g_sumsqf[C * NB];
__device__ float g_a[C];
__device__ float g_b[C];

// ---------------------------------------------------------------------------
// x [C][HW] -> g_xh [HW][C] (fp16), fused fp32 per-position mean/max -> g_stat.
// Block 0 zeroes BN buckets and transposes depth_w -> g_wt (r8 layout).
__global__ void __launch_bounds__(256) transpose_k(const float* __restrict__ x,
                                                   const float* __restrict__ depth_w) {
    __shared__ float tile[C][33];          // [c][hw_local]
    __shared__ float sms[8][32];
    __shared__ float smm[8][32];
    const int hw0 = blockIdx.x * 32;
    const int t  = threadIdx.x;
    const int tx = t & 31, ty = t >> 5;

    if (blockIdx.x == 0) {
        for (int i = t; i < C * NB; i += 256) { g_sumf[i] = 0.f; g_sumsqf[i] = 0.f; }
        for (int i = t; i < KS * C; i += 256) {
            int k = i / C, c = i % C;
            g_wt[k * C + c] = depth_w[c * KS + k];
        }
    }

    float s = 0.f, m = -3.4e38f;
#pragma unroll
    for (int i = 0; i < C; i += 8) {
        float v = __ldcs(x + (size_t)(i + ty) * HW + hw0 + tx);
        tile[i + ty][tx] = v;
        s += v;
        m = fmaxf(m, v);
    }
    sms[ty][tx] = s;
    smm[ty][tx] = m;
    __syncthreads();

    const int hwl = t >> 6;
    const int cp  = t & 63;
#pragma unroll
    for (int i = 0; i < 32; i += 4) {
        const int hw = hwl + i;
        __half2 h = __floats2half2_rn(tile[cp * 2][hw], tile[cp * 2 + 1][hw]);
        *(__half2*)(g_xh + (size_t)(hw0 + hw) * C + cp * 2) = h;
    }
    if (ty == 0) {
        float S = 0.f, M = -3.4e38f;
#pragma unroll
        for (int j = 0; j < 8; j++) { S += sms[j][tx]; M = fmaxf(M, smm[j][tx]); }
        g_stat[hw0 + tx] = make_float2(S * (1.0f / C), M);
    }
}

// ---------------------------------------------------------------------------
// One block = 32 l values — EXACT r8 body (measured best, 120.9us total):
// 288-thread phase2 w/ sast; double-buffered 9-deep gathers; smem w.
__global__ void __launch_bounds__(256, 3) main_k(
    const int*   __restrict__ codes,
    const float* __restrict__ att_w,   // [KS][2][KS]
    const float* __restrict__ att_b,   // [KS]
    const float* __restrict__ depth_b) // [C]
{
    __shared__ float  sm_out[TLB * OSTR];   // [l_local][c] staging
    __shared__ float  sm_w[KS * C];         // depth_w [k][c]
    __shared__ float2 sast[NTASK];          // (avg,max) per (l,k)
    __shared__ float  sm_attp[NTASK];       // 1+sigmoid per (l,o)
    __shared__ float  sm_aw[KS * 2 * KS];
    __shared__ float  sm_ab[KS];
    __shared__ int    sidx[NTASK];

    const int t    = threadIdx.x;
    const int lane = t & 31;
    const int wid  = t >> 5;
    const int l0   = blockIdx.x * TLB;
    const int c0   = lane * 4;

    if (t < KS * 2 * KS) sm_aw[t] = att_w[t];
    if (t < KS)          sm_ab[t] = att_b[t];
    for (int i = t; i < KS * C; i += 256) sm_w[i] = g_wt[i];

    // phase 1: codes + stats
    for (int i = t; i < NTASK; i += 256) {
        int j = __ldg(codes + l0 * KS + i);
        sidx[i] = j;
        sast[i] = g_stat[j];
    }
    __syncthreads();

    // phase 2: attention logits (one thread per (l,o))
    for (int i = t; i < NTASK; i += 256) {
        const int l = i / KS, o = i % KS;
        float a = sm_ab[o];
#pragma unroll
        for (int k = 0; k < KS; k++) {
            float2 st = sast[l * KS + k];
            a += st.x * sm_aw[(o * 2    ) * KS + k]
               + st.y * sm_aw[(o * 2 + 1) * KS + k];
        }
        sm_attp[i] = 1.0f + 1.0f / (1.0f + __expf(-a));
    }
    __syncthreads();

    // phase 3: double-buffered gathers + depthwise
    uint2 vcur[KS], vnxt[KS];
#pragma unroll
    for (int k = 0; k < KS; k++) {
        int j = sidx[wid * KS + k];
        vcur[k] = *(const uint2*)(g_xh + (size_t)j * C + c0);
    }

#pragma unroll
    for (int r = 0; r < ROUNDS; r++) {
        const int ll = r * WPB + wid;

        if (r + 1 < ROUNDS) {
            const int lln = ll + WPB;
#pragma unroll
            for (int k = 0; k < KS; k++) {
                int j = sidx[lln * KS + k];
                vnxt[k] = *(const uint2*)(g_xh + (size_t)j * C + c0);
            }
        }

        float4 acc = make_float4(0.f, 0.f, 0.f, 0.f);
#pragma unroll
        for (int k = 0; k < KS; k++) {
            const float apk = sm_attp[ll * KS + k];     // broadcast LDS
            float4 w4 = *(const float4*)(sm_w + k * C + c0);
            float2 x01 = __half22float2(*(__half2*)&vcur[k].x);
            float2 x23 = __half22float2(*(__half2*)&vcur[k].y);
            acc.x = fmaf(x01.x, apk * w4.x, acc.x);
            acc.y = fmaf(x01.y, apk * w4.y, acc.y);
            acc.z = fmaf(x23.x, apk * w4.z, acc.z);
            acc.w = fmaf(x23.y, apk * w4.w, acc.w);
        }
        *(float4*)(sm_out + ll * OSTR + c0) = acc;

#pragma unroll
        for (int k = 0; k < KS; k++) vcur[k] = vnxt[k];
    }
    __syncthreads();

    // epilogue (r8): fp16 stores to scratch + float BN-stat atomics
    const int c    = t >> 1;
    const int half = t & 1;
    const int q    = l0 >> 14;
    const int rr   = (l0 & (PLANE - 1)) + half * 16;
    const float dbc = depth_b[c];
    __half* ob = g_oh + (size_t)q * (C * PLANE) + (size_t)c * PLANE + rr;

    float s1 = 0.f, s2 = 0.f;
#pragma unroll
    for (int i = 0; i < 4; i++) {
        float4 o4;
        o4.x = sm_out[(half * 16 + i * 4 + 0) * OSTR + c] + dbc;
        o4.y = sm_out[(half * 16 + i * 4 + 1) * OSTR + c] + dbc;
        o4.z = sm_out[(half * 16 + i * 4 + 2) * OSTR + c] + dbc;
        o4.w = sm_out[(half * 16 + i * 4 + 3) * OSTR + c] + dbc;
        s1 += (o4.x + o4.y) + (o4.z + o4.w);
        s2 += o4.x * o4.x + o4.y * o4.y + o4.z * o4.z + o4.w * o4.w;
        __half2 h01 = __floats2half2_rn(o4.x, o4.y);
        __half2 h23 = __floats2half2_rn(o4.z, o4.w);
        *(uint2*)(ob + i * 4) = make_uint2(*(unsigned*)&h01, *(unsigned*)&h23);
    }

    s1 += __shfl_xor_sync(0xffffffffu, s1, 1);
    s2 += __shfl_xor_sync(0xffffffffu, s2, 1);
    if (half == 0) {
        const int bkt = blockIdx.x & (NB - 1);
        atomicAdd(&g_sumf[c * NB + bkt],   s1);
        atomicAdd(&g_sumsqf[c * NB + bkt], s2);
    }
}

// ---------------------------------------------------------------------------
__global__ void bn_params_k(const float* __restrict__ gamma,
                            const float* __restrict__ beta) {
    int t = threadIdx.x;
    int c = t >> 1, half = t & 1;
    double s1 = 0.0, s2 = 0.0;
#pragma unroll
    for (int b = 0; b < NB / 2; b++) {
        int idx = c * NB + half * (NB / 2) + b;
        s1 += (double)g_sumf[idx]; s2 += (double)g_sumsqf[idx];
    }
    s1 += __shfl_xor_sync(0xffffffffu, s1, 1);
    s2 += __shfl_xor_sync(0xffffffffu, s2, 1);
    if (half == 0) {
        double mean = s1 * (1.0 / LTOT);
        double var  = s2 * (1.0 / LTOT) - mean * mean;
        float inv = rsqrtf((float)var + 1e-5f);
        float a = gamma[c] * inv;
        g_a[c] = a;
        g_b[c] = beta[c] - (float)mean * a;
    }
}

// ---------------------------------------------------------------------------
// BN affine + SiLU. 16 halves per thread (2 independent uint4 loads -> 2x MLP
// vs r8), r8's exact arithmetic (full-precision div, plain g_oh loads,
// streaming out stores).
__global__ void finalize_k(float* __restrict__ out) {
    const int i = blockIdx.x * blockDim.x + threadIdx.x;   // 16-half chunk index
    const size_t base = (size_t)i * 16;
    const int c = (int)((base >> 14) & 127);               // (base/PLANE)%C
    const float a = g_a[c], b = g_b[c];

    uint4 h0 = *((const uint4*)g_oh + i * 2);
    uint4 h1 = *((const uint4*)g_oh + i * 2 + 1);

    float4 r[4];
    {
        float2 p0 = __half22float2(*(__half2*)&h0.x);
        float2 p1 = __half22float2(*(__half2*)&h0.y);
        float2 p2 = __half22float2(*(__half2*)&h0.z);
        float2 p3 = __half22float2(*(__half2*)&h0.w);
        r[0].x = fmaf(a, p0.x, b); r[0].y = fmaf(a, p0.y, b);
        r[0].z = fmaf(a, p1.x, b); r[0].w = fmaf(a, p1.y, b);
        r[1].x = fmaf(a, p2.x, b); r[1].y = fmaf(a, p2.y, b);
        r[1].z = fmaf(a, p3.x, b); r[1].w = fmaf(a, p3.y, b);
    }
    {
        float2 p0 = __half22float2(*(__half2*)&h1.x);
        float2 p1 = __half22float2(*(__half2*)&h1.y);
        float2 p2 = __half22float2(*(__half2*)&h1.z);
        float2 p3 = __half22float2(*(__half2*)&h1.w);
        r[2].x = fmaf(a, p0.x, b); r[2].y = fmaf(a, p0.y, b);
        r[2].z = fmaf(a, p1.x, b); r[2].w = fmaf(a, p1.y, b);
        r[3].x = fmaf(a, p2.x, b); r[3].y = fmaf(a, p2.y, b);
        r[3].z = fmaf(a, p3.x, b); r[3].w = fmaf(a, p3.y, b);
    }
#pragma unroll
    for (int j = 0; j < 4; j++) {
        r[j].x = r[j].x / (1.f + __expf(-r[j].x));
        r[j].y = r[j].y / (1.f + __expf(-r[j].y));
        r[j].z = r[j].z / (1.f + __expf(-r[j].z));
        r[j].w = r[j].w / (1.f + __expf(-r[j].w));
        __stcs((float4*)out + i * 4 + j, r[j]);
    }
}

// ---------------------------------------------------------------------------
extern "C" void kernel_launch(void* const* d_in, const int* in_sizes, int n_in,
                              void* d_out, int out_size) {
    const float* x       = (const float*)d_in[0];
    const int*   codes   = (const int*)  d_in[1];
    const float* att_w   = (const float*)d_in[2];
    const float* att_b   = (const float*)d_in[3];
    const float* depth_w = (const float*)d_in[4];
    const float* depth_b = (const float*)d_in[5];
    const float* gamma   = (const float*)d_in[6];
    const float* beta    = (const float*)d_in[7];
    float* out = (float*)d_out;

    transpose_k<<<HW / 32, 256>>>(x, depth_w);
    main_k<<<NBLK, 256>>>(codes, att_w, att_b, depth_b);
    bn_params_k<<<1, 256>>>(gamma, beta);
    finalize_k<<<(LTOT * C / 16) / 256, 256>>>(out);
}

// round 16
// speedup vs baseline: 1.1723x; 1.0775x over previous
#include <cuda_runtime.h>
#include <cuda_fp16.h>

#define HW     131072      // h*w = 256*512
#define C      128
#define LTOT   163840      // Q*M*M
#define KS     9
#define TLB    32          // l-values per block
#define WPB    8           // warps per block
#define ROUNDS (TLB/WPB)
#define NTASK  (TLB*KS)    // 288 (l,k)/(l,o) tasks per block
#define OSTR   132         // padded staging stride (words) per l row
#define PLANE  16384       // M*M
#define NB     16          // BN stat buckets
#define NBLK   (LTOT/TLB)  // 5120 main blocks

// Scratch (allocation-free rule: device globals)
__device__ __align__(16) __half g_xh[(size_t)HW * C];     // transposed x (fp16): [hw][c]
__device__ __align__(16) __half g_oh[(size_t)LTOT * C];   // pre-BN output (fp16)
__device__ __align__(8)  float2 g_stat[HW];               // per-position (mean, max), fp32
__device__ __align__(16) float  g_wt[KS * C];             // depth_w transposed: [k][c]
__device__ float g_sumf[C * NB];
__device__ float g_sumsqf[C * NB];
__device__ float g_a[C];
__device__ float g_b[C];

// ---------------------------------------------------------------------------
// x [C][HW] -> g_xh [HW][C] (fp16), fused fp32 per-position mean/max -> g_stat.
// Block 0 zeroes BN buckets and transposes depth_w -> g_wt. (r8 exact)
__global__ void __launch_bounds__(256) transpose_k(const float* __restrict__ x,
                                                   const float* __restrict__ depth_w) {
    __shared__ float tile[C][33];          // [c][hw_local]
    __shared__ float sms[8][32];
    __shared__ float smm[8][32];
    const int hw0 = blockIdx.x * 32;
    const int t  = threadIdx.x;
    const int tx = t & 31, ty = t >> 5;

    if (blockIdx.x == 0) {
        for (int i = t; i < C * NB; i += 256) { g_sumf[i] = 0.f; g_sumsqf[i] = 0.f; }
        for (int i = t; i < KS * C; i += 256) {
            int k = i / C, c = i % C;
            g_wt[k * C + c] = depth_w[c * KS + k];
        }
    }

    float s = 0.f, m = -3.4e38f;
#pragma unroll
    for (int i = 0; i < C; i += 8) {
        float v = __ldcs(x + (size_t)(i + ty) * HW + hw0 + tx);
        tile[i + ty][tx] = v;
        s += v;
        m = fmaxf(m, v);
    }
    sms[ty][tx] = s;
    smm[ty][tx] = m;
    __syncthreads();

    const int hwl = t >> 6;
    const int cp  = t & 63;
#pragma unroll
    for (int i = 0; i < 32; i += 4) {
        const int hw = hwl + i;
        __half2 h = __floats2half2_rn(tile[cp * 2][hw], tile[cp * 2 + 1][hw]);
        *(__half2*)(g_xh + (size_t)(hw0 + hw) * C + cp * 2) = h;
    }
    if (ty == 0) {
        float S = 0.f, M = -3.4e38f;
#pragma unroll
        for (int j = 0; j < 8; j++) { S += sms[j][tx]; M = fmaxf(M, smm[j][tx]); }
        g_stat[hw0 + tx] = make_float2(S * (1.0f / C), M);
    }
}

// ---------------------------------------------------------------------------
// One block = 32 l values — EXACT r8 body (measured best, 120.9us total).
__global__ void __launch_bounds__(256, 3) main_k(
    const int*   __restrict__ codes,
    const float* __restrict__ att_w,   // [KS][2][KS]
    const float* __restrict__ att_b,   // [KS]
    const float* __restrict__ depth_b) // [C]
{
    __shared__ float  sm_out[TLB * OSTR];   // [l_local][c] staging
    __shared__ float  sm_w[KS * C];         // depth_w [k][c]
    __shared__ float2 sast[NTASK];          // (avg,max) per (l,k)
    __shared__ float  sm_attp[NTASK];       // 1+sigmoid per (l,o)
    __shared__ float  sm_aw[KS * 2 * KS];
    __shared__ float  sm_ab[KS];
    __shared__ int    sidx[NTASK];

    const int t    = threadIdx.x;
    const int lane = t & 31;
    const int wid  = t >> 5;
    const int l0   = blockIdx.x * TLB;
    const int c0   = lane * 4;

    if (t < KS * 2 * KS) sm_aw[t] = att_w[t];
    if (t < KS)          sm_ab[t] = att_b[t];
    for (int i = t; i < KS * C; i += 256) sm_w[i] = g_wt[i];

    // phase 1: codes + stats
    for (int i = t; i < NTASK; i += 256) {
        int j = __ldg(codes + l0 * KS + i);
        sidx[i] = j;
        sast[i] = g_stat[j];
    }
    __syncthreads();

    // phase 2: attention logits (one thread per (l,o))
    for (int i = t; i < NTASK; i += 256) {
        const int l = i / KS, o = i % KS;
        float a = sm_ab[o];
#pragma unroll
        for (int k = 0; k < KS; k++) {
            float2 st = sast[l * KS + k];
            a += st.x * sm_aw[(o * 2    ) * KS + k]
               + st.y * sm_aw[(o * 2 + 1) * KS + k];
        }
        sm_attp[i] = 1.0f + 1.0f / (1.0f + __expf(-a));
    }
    __syncthreads();

    // phase 3: double-buffered gathers + depthwise
    uint2 vcur[KS], vnxt[KS];
#pragma unroll
    for (int k = 0; k < KS; k++) {
        int j = sidx[wid * KS + k];
        vcur[k] = *(const uint2*)(g_xh + (size_t)j * C + c0);
    }

#pragma unroll
    for (int r = 0; r < ROUNDS; r++) {
        const int ll = r * WPB + wid;

        if (r + 1 < ROUNDS) {
            const int lln = ll + WPB;
#pragma unroll
            for (int k = 0; k < KS; k++) {
                int j = sidx[lln * KS + k];
                vnxt[k] = *(const uint2*)(g_xh + (size_t)j * C + c0);
            }
        }

        float4 acc = make_float4(0.f, 0.f, 0.f, 0.f);
#pragma unroll
        for (int k = 0; k < KS; k++) {
            const float apk = sm_attp[ll * KS + k];     // broadcast LDS
            float4 w4 = *(const float4*)(sm_w + k * C + c0);
            float2 x01 = __half22float2(*(__half2*)&vcur[k].x);
            float2 x23 = __half22float2(*(__half2*)&vcur[k].y);
            acc.x = fmaf(x01.x, apk * w4.x, acc.x);
            acc.y = fmaf(x01.y, apk * w4.y, acc.y);
            acc.z = fmaf(x23.x, apk * w4.z, acc.z);
            acc.w = fmaf(x23.y, apk * w4.w, acc.w);
        }
        *(float4*)(sm_out + ll * OSTR + c0) = acc;

#pragma unroll
        for (int k = 0; k < KS; k++) vcur[k] = vnxt[k];
    }
    __syncthreads();

    // epilogue (r8): fp16 stores to scratch + float BN-stat atomics
    const int c    = t >> 1;
    const int half = t & 1;
    const int q    = l0 >> 14;
    const int rr   = (l0 & (PLANE - 1)) + half * 16;
    const float dbc = depth_b[c];
    __half* ob = g_oh + (size_t)q * (C * PLANE) + (size_t)c * PLANE + rr;

    float s1 = 0.f, s2 = 0.f;
#pragma unroll
    for (int i = 0; i < 4; i++) {
        float4 o4;
        o4.x = sm_out[(half * 16 + i * 4 + 0) * OSTR + c] + dbc;
        o4.y = sm_out[(half * 16 + i * 4 + 1) * OSTR + c] + dbc;
        o4.z = sm_out[(half * 16 + i * 4 + 2) * OSTR + c] + dbc;
        o4.w = sm_out[(half * 16 + i * 4 + 3) * OSTR + c] + dbc;
        s1 += (o4.x + o4.y) + (o4.z + o4.w);
        s2 += o4.x * o4.x + o4.y * o4.y + o4.z * o4.z + o4.w * o4.w;
        __half2 h01 = __floats2half2_rn(o4.x, o4.y);
        __half2 h23 = __floats2half2_rn(o4.z, o4.w);
        *(uint2*)(ob + i * 4) = make_uint2(*(unsigned*)&h01, *(unsigned*)&h23);
    }

    s1 += __shfl_xor_sync(0xffffffffu, s1, 1);
    s2 += __shfl_xor_sync(0xffffffffu, s2, 1);
    if (half == 0) {
        const int bkt = blockIdx.x & (NB - 1);
        atomicAdd(&g_sumf[c * NB + bkt],   s1);
        atomicAdd(&g_sumsqf[c * NB + bkt], s2);
    }
}

// ---------------------------------------------------------------------------
// 1024 threads: thread i loads bucket i and i+1024 (one load per array per
// slot, full MLP), fp32 butterfly over the 16-lane bucket group.
__global__ void __launch_bounds__(1024) bn_params_k(const float* __restrict__ gamma,
                                                    const float* __restrict__ beta) {
    const int t = threadIdx.x;
    float s1 = g_sumf[t]   + g_sumf[t + 1024];
    float s2 = g_sumsqf[t] + g_sumsqf[t + 1024];
#pragma unroll
    for (int off = 8; off > 0; off >>= 1) {
        s1 += __shfl_xor_sync(0xffffffffu, s1, off);
        s2 += __shfl_xor_sync(0xffffffffu, s2, off);
    }
    if ((t & (NB - 1)) == 0) {
        // t = c*NB for c = t/NB (and c+64 handled by t+1024 fold)
        int c = t >> 4;        // covers c 0..63 from first half...
        // NOTE: buckets are laid out c*NB+b; t+1024 is c+64. Combine both:
        // s1 here = sum over buckets of c AND c+64. Recompute separately below.
        (void)c;
    }
    // The fold above mixed c and c+64; redo cleanly: each thread group of 16
    // lanes reduced buckets of (c = t/16) plus (c+64). We need them separate,
    // so instead compute per-half sums without the +1024 fold:
    float a1 = g_sumf[t], a2 = g_sumsqf[t];
    float b1 = g_sumf[t + 1024], b2 = g_sumsqf[t + 1024];
#pragma unroll
    for (int off = 8; off > 0; off >>= 1) {
        a1 += __shfl_xor_sync(0xffffffffu, a1, off);
        a2 += __shfl_xor_sync(0xffffffffu, a2, off);
        b1 += __shfl_xor_sync(0xffffffffu, b1, off);
        b2 += __shfl_xor_sync(0xffffffffu, b2, off);
    }
    if ((t & (NB - 1)) == 0) {
        int c = t >> 4;                       // 0..63
        {
            float mean = a1 * (1.0f / LTOT);
            float var  = a2 * (1.0f / LTOT) - mean * mean;
            float inv = rsqrtf(var + 1e-5f);
            float ga = gamma[c] * inv;
            g_a[c] = ga;
            g_b[c] = beta[c] - mean * ga;
        }
        {
            int c2 = c + 64;
            float mean = b1 * (1.0f / LTOT);
            float var  = b2 * (1.0f / LTOT) - mean * mean;
            float inv = rsqrtf(var + 1e-5f);
            float ga = gamma[c2] * inv;
            g_a[c2] = ga;
            g_b[c2] = beta[c2] - mean * ga;
        }
    }
}

// ---------------------------------------------------------------------------
// r8-exact finalize: 8 halves/thread, plain g_oh loads, plain div, .cs stores.
__global__ void finalize_k(float* __restrict__ out) {
    const int i = blockIdx.x * blockDim.x + threadIdx.x;   // 8-half chunk index
    const size_t base = (size_t)i * 8;
    const int c = (int)((base >> 14) & 127);               // (base/PLANE)%C
    const float a = g_a[c], b = g_b[c];

    uint4 h = *((const uint4*)g_oh + i);
    float2 p0 = __half22float2(*(__half2*)&h.x);
    float2 p1 = __half22float2(*(__half2*)&h.y);
    float2 p2 = __half22float2(*(__half2*)&h.z);
    float2 p3 = __half22float2(*(__half2*)&h.w);

    float4 r0, r1;
    r0.x = a * p0.x + b;  r0.x = r0.x / (1.f + __expf(-r0.x));
    r0.y = a * p0.y + b;  r0.y = r0.y / (1.f + __expf(-r0.y));
    r0.z = a * p1.x + b;  r0.z = r0.z / (1.f + __expf(-r0.z));
    r0.w = a * p1.y + b;  r0.w = r0.w / (1.f + __expf(-r0.w));
    r1.x = a * p2.x + b;  r1.x = r1.x / (1.f + __expf(-r1.x));
    r1.y = a * p2.y + b;  r1.y = r1.y / (1.f + __expf(-r1.y));
    r1.z = a * p3.x + b;  r1.z = r1.z / (1.f + __expf(-r1.z));
    r1.w = a * p3.y + b;  r1.w = r1.w / (1.f + __expf(-r1.w));

    __stcs((float4*)out + i * 2,     r0);
    __stcs((float4*)out + i * 2 + 1, r1);
}

// ---------------------------------------------------------------------------
extern "C" void kernel_launch(void* const* d_in, const int* in_sizes, int n_in,
                              void* d_out, int out_size) {
    const float* x       = (const float*)d_in[0];
    const int*   codes   = (const int*)  d_in[1];
    const float* att_w   = (const float*)d_in[2];
    const float* att_b   = (const float*)d_in[3];
    const float* depth_w = (const float*)d_in[4];
    const float* depth_b = (const float*)d_in[5];
    const float* gamma   = (const float*)d_in[6];
    const float* beta    = (const float*)d_in[7];
    float* out = (float*)d_out;

    transpose_k<<<HW / 32, 256>>>(x, depth_w);
    main_k<<<NBLK, 256>>>(codes, att_w, att_b, depth_b);
    bn_params_k<<<1, 1024>>>(gamma, beta);
    finalize_k<<<(LTOT * C / 8) / 256, 256>>>(out);
}

// round 17
// speedup vs baseline: 1.1929x; 1.0175x over previous
#include <cuda_runtime.h>
#include <cuda_fp16.h>

#define HW     131072      // h*w = 256*512
#define C      128
#define LTOT   163840      // Q*M*M
#define KS     9
#define TLB    32          // l-values per block
#define WPB    8           // warps per block
#define ROUNDS (TLB/WPB)
#define NTASK  (TLB*KS)    // 288 (l,k)/(l,o) tasks per block
#define OSTR   132         // padded staging stride (words) per l row
#define PLANE  16384       // M*M
#define NB     16          // BN stat buckets
#define NBLK   (LTOT/TLB)  // 5120 main blocks

// Scratch (allocation-free rule: device globals)
__device__ __align__(16) __half g_xh[(size_t)HW * C];     // transposed x (fp16): [hw][c]
__device__ __align__(16) __half g_oh[(size_t)LTOT * C];   // pre-BN output (fp16)
__device__ __align__(8)  float2 g_stat[HW];               // per-position (mean, max), fp32
__device__ __align__(16) float  g_wt[KS * C];             // depth_w transposed: [k][c]
__device__ float g_sumf[C * NB];
__device__ float g_sumsqf[C * NB];
__device__ float g_a[C];
__device__ float g_b[C];

__device__ __forceinline__ float tanh_fast(float x) {
    float r;
    asm("tanh.approx.f32 %0, %1;" : "=f"(r) : "f"(x));
    return r;
}
// silu(v) = v * sigmoid(v) = h*tanh(h) + h, h = v/2
__device__ __forceinline__ float silu_t(float v) {
    float h = 0.5f * v;
    return fmaf(h, tanh_fast(h), h);
}

// ---------------------------------------------------------------------------
// x [C][HW] -> g_xh [HW][C] (fp16), fused fp32 per-position mean/max -> g_stat.
// Block 0 zeroes BN buckets and transposes depth_w -> g_wt. (r8/r16 exact)
__global__ void __launch_bounds__(256) transpose_k(const float* __restrict__ x,
                                                   const float* __restrict__ depth_w) {
    __shared__ float tile[C][33];          // [c][hw_local]
    __shared__ float sms[8][32];
    __shared__ float smm[8][32];
    const int hw0 = blockIdx.x * 32;
    const int t  = threadIdx.x;
    const int tx = t & 31, ty = t >> 5;

    if (blockIdx.x == 0) {
        for (int i = t; i < C * NB; i += 256) { g_sumf[i] = 0.f; g_sumsqf[i] = 0.f; }
        for (int i = t; i < KS * C; i += 256) {
            int k = i / C, c = i % C;
            g_wt[k * C + c] = depth_w[c * KS + k];
        }
    }

    float s = 0.f, m = -3.4e38f;
#pragma unroll
    for (int i = 0; i < C; i += 8) {
        float v = __ldcs(x + (size_t)(i + ty) * HW + hw0 + tx);
        tile[i + ty][tx] = v;
        s += v;
        m = fmaxf(m, v);
    }
    sms[ty][tx] = s;
    smm[ty][tx] = m;
    __syncthreads();

    const int hwl = t >> 6;
    const int cp  = t & 63;
#pragma unroll
    for (int i = 0; i < 32; i += 4) {
        const int hw = hwl + i;
        __half2 h = __floats2half2_rn(tile[cp * 2][hw], tile[cp * 2 + 1][hw]);
        *(__half2*)(g_xh + (size_t)(hw0 + hw) * C + cp * 2) = h;
    }
    if (ty == 0) {
        float S = 0.f, M = -3.4e38f;
#pragma unroll
        for (int j = 0; j < 8; j++) { S += sms[j][tx]; M = fmaxf(M, smm[j][tx]); }
        g_stat[hw0 + tx] = make_float2(S * (1.0f / C), M);
    }
}

// ---------------------------------------------------------------------------
// One block = 32 l values — r8 body (measured best); attention sigmoid now
// via tanh.approx (1+sigmoid(a) = 1.5 + 0.5*tanh(a/2)).
__global__ void __launch_bounds__(256, 3) main_k(
    const int*   __restrict__ codes,
    const float* __restrict__ att_w,   // [KS][2][KS]
    const float* __restrict__ att_b,   // [KS]
    const float* __restrict__ depth_b) // [C]
{
    __shared__ float  sm_out[TLB * OSTR];   // [l_local][c] staging
    __shared__ float  sm_w[KS * C];         // depth_w [k][c]
    __shared__ float2 sast[NTASK];          // (avg,max) per (l,k)
    __shared__ float  sm_attp[NTASK];       // 1+sigmoid per (l,o)
    __shared__ float  sm_aw[KS * 2 * KS];
    __shared__ float  sm_ab[KS];
    __shared__ int    sidx[NTASK];

    const int t    = threadIdx.x;
    const int lane = t & 31;
    const int wid  = t >> 5;
    const int l0   = blockIdx.x * TLB;
    const int c0   = lane * 4;

    if (t < KS * 2 * KS) sm_aw[t] = att_w[t];
    if (t < KS)          sm_ab[t] = att_b[t];
    for (int i = t; i < KS * C; i += 256) sm_w[i] = g_wt[i];

    // phase 1: codes + stats
    for (int i = t; i < NTASK; i += 256) {
        int j = __ldg(codes + l0 * KS + i);
        sidx[i] = j;
        sast[i] = g_stat[j];
    }
    __syncthreads();

    // phase 2: attention logits (one thread per (l,o))
    for (int i = t; i < NTASK; i += 256) {
        const int l = i / KS, o = i % KS;
        float a = sm_ab[o];
#pragma unroll
        for (int k = 0; k < KS; k++) {
            float2 st = sast[l * KS + k];
            a += st.x * sm_aw[(o * 2    ) * KS + k]
               + st.y * sm_aw[(o * 2 + 1) * KS + k];
        }
        sm_attp[i] = fmaf(0.5f, tanh_fast(0.5f * a), 1.5f);
    }
    __syncthreads();

    // phase 3: double-buffered gathers + depthwise
    uint2 vcur[KS], vnxt[KS];
#pragma unroll
    for (int k = 0; k < KS; k++) {
        int j = sidx[wid * KS + k];
        vcur[k] = *(const uint2*)(g_xh + (size_t)j * C + c0);
    }

#pragma unroll
    for (int r = 0; r < ROUNDS; r++) {
        const int ll = r * WPB + wid;

        if (r + 1 < ROUNDS) {
            const int lln = ll + WPB;
#pragma unroll
            for (int k = 0; k < KS; k++) {
                int j = sidx[lln * KS + k];
                vnxt[k] = *(const uint2*)(g_xh + (size_t)j * C + c0);
            }
        }

        float4 acc = make_float4(0.f, 0.f, 0.f, 0.f);
#pragma unroll
        for (int k = 0; k < KS; k++) {
            const float apk = sm_attp[ll * KS + k];     // broadcast LDS
            float4 w4 = *(const float4*)(sm_w + k * C + c0);
            float2 x01 = __half22float2(*(__half2*)&vcur[k].x);
            float2 x23 = __half22float2(*(__half2*)&vcur[k].y);
            acc.x = fmaf(x01.x, apk * w4.x, acc.x);
            acc.y = fmaf(x01.y, apk * w4.y, acc.y);
            acc.z = fmaf(x23.x, apk * w4.z, acc.z);
            acc.w = fmaf(x23.y, apk * w4.w, acc.w);
        }
        *(float4*)(sm_out + ll * OSTR + c0) = acc;

#pragma unroll
        for (int k = 0; k < KS; k++) vcur[k] = vnxt[k];
    }
    __syncthreads();

    // epilogue (r8): fp16 stores to scratch + float BN-stat atomics
    const int c    = t >> 1;
    const int half = t & 1;
    const int q    = l0 >> 14;
    const int rr   = (l0 & (PLANE - 1)) + half * 16;
    const float dbc = depth_b[c];
    __half* ob = g_oh + (size_t)q * (C * PLANE) + (size_t)c * PLANE + rr;

    float s1 = 0.f, s2 = 0.f;
#pragma unroll
    for (int i = 0; i < 4; i++) {
        float4 o4;
        o4.x = sm_out[(half * 16 + i * 4 + 0) * OSTR + c] + dbc;
        o4.y = sm_out[(half * 16 + i * 4 + 1) * OSTR + c] + dbc;
        o4.z = sm_out[(half * 16 + i * 4 + 2) * OSTR + c] + dbc;
        o4.w = sm_out[(half * 16 + i * 4 + 3) * OSTR + c] + dbc;
        s1 += (o4.x + o4.y) + (o4.z + o4.w);
        s2 += o4.x * o4.x + o4.y * o4.y + o4.z * o4.z + o4.w * o4.w;
        __half2 h01 = __floats2half2_rn(o4.x, o4.y);
        __half2 h23 = __floats2half2_rn(o4.z, o4.w);
        *(uint2*)(ob + i * 4) = make_uint2(*(unsigned*)&h01, *(unsigned*)&h23);
    }

    s1 += __shfl_xor_sync(0xffffffffu, s1, 1);
    s2 += __shfl_xor_sync(0xffffffffu, s2, 1);
    if (half == 0) {
        const int bkt = blockIdx.x & (NB - 1);
        atomicAdd(&g_sumf[c * NB + bkt],   s1);
        atomicAdd(&g_sumsqf[c * NB + bkt], s2);
    }
}

// ---------------------------------------------------------------------------
// 1024 threads, one bucket load per thread per array half, butterfly reduce.
__global__ void __launch_bounds__(1024) bn_params_k(const float* __restrict__ gamma,
                                                    const float* __restrict__ beta) {
    const int t = threadIdx.x;
    float a1 = g_sumf[t], a2 = g_sumsqf[t];
    float b1 = g_sumf[t + 1024], b2 = g_sumsqf[t + 1024];
#pragma unroll
    for (int off = 8; off > 0; off >>= 1) {
        a1 += __shfl_xor_sync(0xffffffffu, a1, off);
        a2 += __shfl_xor_sync(0xffffffffu, a2, off);
        b1 += __shfl_xor_sync(0xffffffffu, b1, off);
        b2 += __shfl_xor_sync(0xffffffffu, b2, off);
    }
    if ((t & (NB - 1)) == 0) {
        int c = t >> 4;                       // 0..63
        {
            float mean = a1 * (1.0f / LTOT);
            float var  = a2 * (1.0f / LTOT) - mean * mean;
            float inv = rsqrtf(var + 1e-5f);
            float ga = gamma[c] * inv;
            g_a[c] = ga;
            g_b[c] = beta[c] - mean * ga;
        }
        {
            int c2 = c + 64;
            float mean = b1 * (1.0f / LTOT);
            float var  = b2 * (1.0f / LTOT) - mean * mean;
            float inv = rsqrtf(var + 1e-5f);
            float ga = gamma[c2] * inv;
            g_a[c2] = ga;
            g_b[c2] = beta[c2] - mean * ga;
        }
    }
}

// ---------------------------------------------------------------------------
// finalize: 8 halves/thread (r8 structure), SiLU via tanh.approx (3 instr
// per value instead of ~9 — kernel was 64.5% issue-bound).
__global__ void finalize_k(float* __restrict__ out) {
    const int i = blockIdx.x * blockDim.x + threadIdx.x;   // 8-half chunk index
    const size_t base = (size_t)i * 8;
    const int c = (int)((base >> 14) & 127);               // (base/PLANE)%C
    const float a = g_a[c], b = g_b[c];

    uint4 h = *((const uint4*)g_oh + i);
    float2 p0 = __half22float2(*(__half2*)&h.x);
    float2 p1 = __half22float2(*(__half2*)&h.y);
    float2 p2 = __half22float2(*(__half2*)&h.z);
    float2 p3 = __half22float2(*(__half2*)&h.w);

    float4 r0, r1;
    r0.x = silu_t(fmaf(a, p0.x, b));
    r0.y = silu_t(fmaf(a, p0.y, b));
    r0.z = silu_t(fmaf(a, p1.x, b));
    r0.w = silu_t(fmaf(a, p1.y, b));
    r1.x = silu_t(fmaf(a, p2.x, b));
    r1.y = silu_t(fmaf(a, p2.y, b));
    r1.z = silu_t(fmaf(a, p3.x, b));
    r1.w = silu_t(fmaf(a, p3.y, b));

    __stcs((float4*)out + i * 2,     r0);
    __stcs((float4*)out + i * 2 + 1, r1);
}

// ---------------------------------------------------------------------------
extern "C" void kernel_launch(void* const* d_in, const int* in_sizes, int n_in,
                              void* d_out, int out_size) {
    const float* x       = (const float*)d_in[0];
    const int*   codes   = (const int*)  d_in[1];
    const float* att_w   = (const float*)d_in[2];
    const float* att_b   = (const float*)d_in[3];
    const float* depth_w = (const float*)d_in[4];
    const float* depth_b = (const float*)d_in[5];
    const float* gamma   = (const float*)d_in[6];
    const float* beta    = (const float*)d_in[7];
    float* out = (float*)d_out;

    transpose_k<<<HW / 32, 256>>>(x, depth_w);
    main_k<<<NBLK, 256>>>(codes, att_w, att_b, depth_b);
    bn_params_k<<<1, 1024>>>(gamma, beta);
    finalize_k<<<(LTOT * C / 8) / 256, 256>>>(out);
}